// round 16
// baseline (speedup 1.0000x reference)
#include <cuda_runtime.h>
#include <cuda_bf16.h>
#include <cstdint>
#include <math.h>

#define NMAX 100000
#define EMAX 1600000
#define HDIM 64
#define LMAX 2
#define K1B 512   // B1 row: [hi(4x64) | lo(4x64)]
#define K2B 256   // B2 row: [hi(2x64) | lo(2x64)]

// ---------------- scratch (static device memory) ---------------------------
__device__ __align__(16) int   g_deg[NMAX];
__device__ __align__(16) int   g_rowptr[NMAX + 1];
__device__ __align__(16) int   g_cursor[NMAX];
__device__ __align__(16) int   g_csr[EMAX];
__device__ __align__(16) float g_invdeg[NMAX];
__device__ __align__(16) int   g_bsum[512];

__device__ __align__(16) float g_AGX[(size_t)NMAX * HDIM];  // mean-agg of x
__device__ __align__(16) float g_AGH[(size_t)NMAX * HDIM];  // mean-agg of h
__device__ __align__(16) float g_AG2[(size_t)NMAX * HDIM];  // mean-agg of r*h
__device__ __align__(16) float g_Z [(size_t)NMAX * HDIM];
__device__ __align__(16) float g_TP[(size_t)NMAX * HDIM];
__device__ __align__(16) float g_RH[(size_t)NMAX * HDIM];

__device__ __align__(16) __nv_bfloat16 g_Bt1[(size_t)LMAX * 192 * K1B];
__device__ __align__(16) __nv_bfloat16 g_Bt2[(size_t)LMAX * 64 * K2B];
__device__ __align__(16) float g_bias1[LMAX * 192];
__device__ __align__(16) float g_bias2[LMAX * 64];

// ---------------- helpers --------------------------------------------------
__device__ __forceinline__ float sigm(float x) { return 1.0f / (1.0f + __expf(-x)); }
__device__ __forceinline__ float fast_tanh(float x) {
    float xc = fminf(fmaxf(x, -30.0f), 30.0f);
    return 1.0f - __fdividef(2.0f, __expf(2.0f * xc) + 1.0f);
}

__device__ __forceinline__ void mma_bf16(float (&d)[4], const uint32_t (&a)[4],
                                         const uint32_t (&b)[2]) {
    asm volatile(
        "mma.sync.aligned.m16n8k16.row.col.f32.bf16.bf16.f32 "
        "{%0,%1,%2,%3}, {%4,%5,%6,%7}, {%8,%9}, {%0,%1,%2,%3};\n"
        : "+f"(d[0]), "+f"(d[1]), "+f"(d[2]), "+f"(d[3])
        : "r"(a[0]), "r"(a[1]), "r"(a[2]), "r"(a[3]), "r"(b[0]), "r"(b[1]));
}
__device__ __forceinline__ uint32_t sptr(const void* p) {
    return (uint32_t)__cvta_generic_to_shared(p);
}
__device__ __forceinline__ void ldsm_x4(uint32_t (&r)[4], uint32_t addr) {
    asm volatile("ldmatrix.sync.aligned.m8n8.x4.shared.b16 {%0,%1,%2,%3}, [%4];\n"
                 : "=r"(r[0]), "=r"(r[1]), "=r"(r[2]), "=r"(r[3]) : "r"(addr));
}
__device__ __forceinline__ void cp_async16(uint32_t dst, const void* src) {
    asm volatile("cp.async.cg.shared.global [%0], [%1], 16;\n" :: "r"(dst), "l"(src));
}
__device__ __forceinline__ void cp_async_commit() {
    asm volatile("cp.async.commit_group;\n");
}
__device__ __forceinline__ void cp_async_wait_all() {
    asm volatile("cp.async.wait_group 0;\n" ::: "memory");
}
__device__ __forceinline__ void split_pack2(float a, float b, uint32_t& hi2, uint32_t& lo2) {
    __nv_bfloat16 ha = __float2bfloat16_rn(a), hb = __float2bfloat16_rn(b);
    __nv_bfloat16 la = __float2bfloat16_rn(a - __bfloat162float(ha));
    __nv_bfloat16 lb = __float2bfloat16_rn(b - __bfloat162float(hb));
    hi2 = ((uint32_t)__bfloat16_as_ushort(hb) << 16) | __bfloat16_as_ushort(ha);
    lo2 = ((uint32_t)__bfloat16_as_ushort(lb) << 16) | __bfloat16_as_ushort(la);
}

// ---------------- CSR build ------------------------------------------------
__global__ void k_zero_deg(int N) {
    int i = blockIdx.x * blockDim.x + threadIdx.x;
    if (i < N) g_deg[i] = 0;
}

// vectorized: one thread handles 4 consecutive edges via int4 (coalesced)
__global__ void k_count4(const int* __restrict__ edg, int E, int N) {
    int t = blockIdx.x * blockDim.x + threadIdx.x;
    int base = t * 4;
    if (base >= E) return;
    int4 d = *(const int4*)(edg + E + base);
    if ((unsigned)d.x < (unsigned)N) atomicAdd(&g_deg[d.x], 1);
    if ((unsigned)d.y < (unsigned)N) atomicAdd(&g_deg[d.y], 1);
    if ((unsigned)d.z < (unsigned)N) atomicAdd(&g_deg[d.z], 1);
    if ((unsigned)d.w < (unsigned)N) atomicAdd(&g_deg[d.w], 1);
}
__global__ void k_count(const int* __restrict__ edg, int E, int N) {
    int e = blockIdx.x * blockDim.x + threadIdx.x;
    if (e < E) {
        int dst = edg[E + e];
        if ((unsigned)dst < (unsigned)N) atomicAdd(&g_deg[dst], 1);
    }
}

__global__ void k_scan1(int N) {
    __shared__ int ws[8];
    int tid = threadIdx.x, lane = tid & 31, wid = tid >> 5;
    int i = blockIdx.x * 256 + tid;
    int v = (i < N) ? g_deg[i] : 0;
    int x = v;
    #pragma unroll
    for (int o = 1; o < 32; o <<= 1) x += __shfl_down_sync(0xffffffffu, x, o);
    if (lane == 0) ws[wid] = x;
    __syncthreads();
    if (tid == 0) {
        int s = 0;
        #pragma unroll
        for (int w = 0; w < 8; w++) s += ws[w];
        g_bsum[blockIdx.x] = s;
    }
}

__global__ void k_scan2(int nb, int N) {
    __shared__ int ws[16];
    int tid = threadIdx.x, lane = tid & 31, wid = tid >> 5;
    int v = (tid < nb) ? g_bsum[tid] : 0;
    int x = v;
    #pragma unroll
    for (int o = 1; o < 32; o <<= 1) {
        int y = __shfl_up_sync(0xffffffffu, x, o);
        if (lane >= o) x += y;
    }
    if (lane == 31) ws[wid] = x;
    __syncthreads();
    if (wid == 0 && lane < 16) {
        int w = ws[lane];
        #pragma unroll
        for (int o = 1; o < 16; o <<= 1) {
            int y = __shfl_up_sync(0xffffu, w, o);
            if (lane >= o) w += y;
        }
        ws[lane] = w;
    }
    __syncthreads();
    int excl = x - v + (wid > 0 ? ws[wid - 1] : 0);
    if (tid < nb) g_bsum[tid] = excl;
    if (tid == nb - 1) g_rowptr[N] = excl + v;
}

__global__ void k_scan3(int N) {
    __shared__ int ws[8];
    int tid = threadIdx.x, lane = tid & 31, wid = tid >> 5;
    int i = blockIdx.x * 256 + tid;
    int v = (i < N) ? g_deg[i] : 0;
    int x = v;
    #pragma unroll
    for (int o = 1; o < 32; o <<= 1) {
        int y = __shfl_up_sync(0xffffffffu, x, o);
        if (lane >= o) x += y;
    }
    if (lane == 31) ws[wid] = x;
    __syncthreads();
    if (wid == 0 && lane < 8) {
        int w = ws[lane];
        #pragma unroll
        for (int o = 1; o < 8; o <<= 1) {
            int y = __shfl_up_sync(0xffu, w, o);
            if (lane >= o) w += y;
        }
        ws[lane] = w;
    }
    __syncthreads();
    if (i < N) {
        int excl = x - v + (wid > 0 ? ws[wid - 1] : 0) + g_bsum[blockIdx.x];
        g_rowptr[i] = excl;
        g_cursor[i] = excl;
        g_invdeg[i] = (v > 0) ? 1.0f / (float)v : 0.0f;
    }
}

__global__ void k_scatter4(const int* __restrict__ edg, int E, int N) {
    int t = blockIdx.x * blockDim.x + threadIdx.x;
    int base = t * 4;
    if (base >= E) return;
    int4 s = *(const int4*)(edg + base);
    int4 d = *(const int4*)(edg + E + base);
    if ((unsigned)s.x < (unsigned)N && (unsigned)d.x < (unsigned)N)
        g_csr[atomicAdd(&g_cursor[d.x], 1)] = s.x;
    if ((unsigned)s.y < (unsigned)N && (unsigned)d.y < (unsigned)N)
        g_csr[atomicAdd(&g_cursor[d.y], 1)] = s.y;
    if ((unsigned)s.z < (unsigned)N && (unsigned)d.z < (unsigned)N)
        g_csr[atomicAdd(&g_cursor[d.z], 1)] = s.z;
    if ((unsigned)s.w < (unsigned)N && (unsigned)d.w < (unsigned)N)
        g_csr[atomicAdd(&g_cursor[d.w], 1)] = s.w;
}
__global__ void k_scatter(const int* __restrict__ edg, int E, int N) {
    int e = blockIdx.x * blockDim.x + threadIdx.x;
    if (e < E) {
        int src = edg[e];
        int dst = edg[E + e];
        if ((unsigned)src < (unsigned)N && (unsigned)dst < (unsigned)N) {
            int pos = atomicAdd(&g_cursor[dst], 1);
            g_csr[pos] = src;
        }
    }
}

// ---------------- weight / bias packing (single kernel) ---------------------
__global__ void k_packAll(const float* __restrict__ Wl, const float* __restrict__ b,
                          const float* __restrict__ Wr, int L) {
    int idx = blockIdx.x * blockDim.x + threadIdx.x;
    int t1 = L * 192 * K1B;
    int t2 = L * 64 * K2B;
    int t3 = L * 256;
    if (idx < t1) {
        int k = idx % K1B;
        int j = (idx / K1B) % 192;
        int l = idx / (K1B * 192);
        int t = k / 256, rem = k % 256, s = rem / 64, c = rem % 64;
        int g = j / 64, jj = j % 64;
        int gbase = 2 * g;
        float w = 0.0f;
        if (s == 0)      w = Wl[(((size_t)l * 6 + gbase) * 64 + jj) * 64 + c];
        else if (s == 1) w = Wr[(((size_t)l * 6 + gbase) * 64 + jj) * 64 + c];
        else if (s == 2) { if (g < 2) w = Wl[(((size_t)l * 6 + gbase + 1) * 64 + jj) * 64 + c]; }
        else             { if (g < 2) w = Wr[(((size_t)l * 6 + gbase + 1) * 64 + jj) * 64 + c]; }
        __nv_bfloat16 hi = __float2bfloat16_rn(w);
        __nv_bfloat16 val = (t == 1) ? __float2bfloat16_rn(w - __bfloat162float(hi)) : hi;
        g_Bt1[(size_t)(l * 192 + j) * K1B + k] = val;
    } else if (idx < t1 + t2) {
        int i2 = idx - t1;
        int k = i2 % K2B;
        int j = (i2 / K2B) % 64;
        int l = i2 / (K2B * 64);
        int t = k / 128, rem = k % 128, s = rem / 64, c = rem % 64;
        const float* W = s ? Wr : Wl;
        float w = W[(((size_t)l * 6 + 5) * 64 + j) * 64 + c];
        __nv_bfloat16 hi = __float2bfloat16_rn(w);
        __nv_bfloat16 val = (t == 1) ? __float2bfloat16_rn(w - __bfloat162float(hi)) : hi;
        g_Bt2[(size_t)(l * 64 + j) * K2B + k] = val;
    } else if (idx < t1 + t2 + t3) {
        int i3 = idx - t1 - t2;
        int j = i3 % 256, l = i3 / 256;
        if (j < 192) {
            int g = j / 64, jj = j % 64;
            float v;
            if (g == 0)      v = b[((size_t)l * 6 + 0) * 64 + jj] + b[((size_t)l * 6 + 1) * 64 + jj];
            else if (g == 1) v = b[((size_t)l * 6 + 2) * 64 + jj] + b[((size_t)l * 6 + 3) * 64 + jj];
            else             v = b[((size_t)l * 6 + 4) * 64 + jj];
            g_bias1[l * 192 + j] = v;
        } else {
            int jj = j - 192;
            g_bias2[l * 64 + jj] = b[((size_t)l * 6 + 5) * 64 + jj];
        }
    }
}

// ---------------- aggregation (R4 form: warp per node, scalar gather) ------
__global__ void k_agg1(const float* __restrict__ x, const float* __restrict__ h, int N) {
    int warp = (blockIdx.x * blockDim.x + threadIdx.x) >> 5;
    if (warp >= N) return;
    int lane = threadIdx.x & 31;
    int beg = g_rowptr[warp], end = g_rowptr[warp + 1];
    float sx0 = 0.f, sx1 = 0.f, sh0 = 0.f, sh1 = 0.f;
    int e = beg;
    for (; e + 1 < end; e += 2) {
        int s0 = g_csr[e], s1 = g_csr[e + 1];
        const float* xr0 = x + (size_t)s0 * HDIM;
        const float* hr0 = h + (size_t)s0 * HDIM;
        const float* xr1 = x + (size_t)s1 * HDIM;
        const float* hr1 = h + (size_t)s1 * HDIM;
        sx0 += xr0[lane] + xr1[lane];
        sx1 += xr0[lane + 32] + xr1[lane + 32];
        sh0 += hr0[lane] + hr1[lane];
        sh1 += hr0[lane + 32] + hr1[lane + 32];
    }
    if (e < end) {
        int s = g_csr[e];
        const float* xr = x + (size_t)s * HDIM;
        const float* hr = h + (size_t)s * HDIM;
        sx0 += xr[lane];  sx1 += xr[lane + 32];
        sh0 += hr[lane];  sh1 += hr[lane + 32];
    }
    float inv = g_invdeg[warp];
    size_t o = (size_t)warp * HDIM;
    g_AGX[o + lane] = sx0 * inv;  g_AGX[o + lane + 32] = sx1 * inv;
    g_AGH[o + lane] = sh0 * inv;  g_AGH[o + lane + 32] = sh1 * inv;
}

__global__ void k_agg2(int N) {
    int warp = (blockIdx.x * blockDim.x + threadIdx.x) >> 5;
    if (warp >= N) return;
    int lane = threadIdx.x & 31;
    int beg = g_rowptr[warp], end = g_rowptr[warp + 1];
    float s0 = 0.f, s1 = 0.f;
    int e = beg;
    for (; e + 1 < end; e += 2) {
        const float* r0 = g_RH + (size_t)g_csr[e] * HDIM;
        const float* r1 = g_RH + (size_t)g_csr[e + 1] * HDIM;
        s0 += r0[lane] + r1[lane];
        s1 += r0[lane + 32] + r1[lane + 32];
    }
    if (e < end) {
        const float* rr = g_RH + (size_t)g_csr[e] * HDIM;
        s0 += rr[lane];
        s1 += rr[lane + 32];
    }
    float inv = g_invdeg[warp];
    size_t o = (size_t)warp * HDIM;
    g_AG2[o + lane] = s0 * inv;
    g_AG2[o + lane + 32] = s1 * inv;
}

// ---------------- GEMM 1: N-split for 2 CTAs/SM ----------------------------
// grid (rowTiles, 2); 256 threads, 8 warps (4M x 2N), BM=128, BN=96/block,
// warp tile 32x48. smem: A 36.9KB + B double-buf 55.3KB = 90KB -> 2 CTA/SM.
#define BM 128
#define SMPAD 72
#define G1_BSTRIDE (2 * 96 * SMPAD)      // one buffer: hi 96 rows + lo 96 rows
#define GEMM1_SMEM ((2 * 128 * SMPAD + 2 * G1_BSTRIDE) * 2)   // 92160 bytes

__global__ void __launch_bounds__(256) k_gemm1(int N, int l,
                                               const float* __restrict__ xptr,
                                               const float* __restrict__ hptr) {
    extern __shared__ __nv_bfloat16 sm[];
    __nv_bfloat16* AsHi = sm;
    __nv_bfloat16* AsLo = AsHi + 128 * SMPAD;
    __nv_bfloat16* BsBase = AsLo + 128 * SMPAD;

    int n0 = blockIdx.x * BM;
    int gHalf = blockIdx.y;              // 0: cols 0..95, 1: cols 96..191
    int tid = threadIdx.x;
    int wid = tid >> 5, lane = tid & 31;
    int warpM = wid >> 1, warpN = wid & 1;

    float acc[2][6][4];
    #pragma unroll
    for (int mt = 0; mt < 2; mt++)
        #pragma unroll
        for (int nt = 0; nt < 6; nt++)
            #pragma unroll
            for (int q = 0; q < 4; q++) acc[mt][nt][q] = 0.f;

    // B rows for this block: j in [gHalf*96, gHalf*96+96)
    const __nv_bfloat16* Bg = g_Bt1 + ((size_t)l * 192 + gHalf * 96) * K1B;

    float4 aPre[8];
    #pragma unroll
    for (int i = 0; i < 8; i++) {
        int idx = tid + i * 256;
        int r = idx >> 4, q4 = idx & 15;
        aPre[i] = (n0 + r < N)
                ? *(const float4*)(g_AGX + (size_t)(n0 + r) * HDIM + q4 * 4)
                : make_float4(0.f, 0.f, 0.f, 0.f);
    }
    {
        __nv_bfloat16* BH = BsBase;
        __nv_bfloat16* BL = BsBase + 96 * SMPAD;
        #pragma unroll
        for (int i = 0; i < 3; i++) {
            int idx = tid + i * 256;
            int j = idx >> 3, c8 = idx & 7;
            cp_async16(sptr(BH + j * SMPAD + c8 * 8), Bg + (size_t)j * K1B + c8 * 8);
            cp_async16(sptr(BL + j * SMPAD + c8 * 8), Bg + (size_t)j * K1B + 256 + c8 * 8);
        }
        cp_async_commit();
    }

    // source order: 0=aggx 1=x 2=aggh 3=h
    #pragma unroll 1
    for (int s = 0; s < 4; s++) {
        #pragma unroll
        for (int i = 0; i < 8; i++) {
            int idx = tid + i * 256;
            int r = idx >> 4, q4 = idx & 15;
            uint32_t h0, l0, h1, l1;
            split_pack2(aPre[i].x, aPre[i].y, h0, l0);
            split_pack2(aPre[i].z, aPre[i].w, h1, l1);
            *(uint2*)(AsHi + r * SMPAD + q4 * 4) = make_uint2(h0, h1);
            *(uint2*)(AsLo + r * SMPAD + q4 * 4) = make_uint2(l0, l1);
        }
        cp_async_wait_all();
        __syncthreads();

        if (s < 3) {
            const float* Snext = (s == 0) ? xptr : (s == 1) ? g_AGH : hptr;
            #pragma unroll
            for (int i = 0; i < 8; i++) {
                int idx = tid + i * 256;
                int r = idx >> 4, q4 = idx & 15;
                aPre[i] = (n0 + r < N)
                        ? *(const float4*)(Snext + (size_t)(n0 + r) * HDIM + q4 * 4)
                        : make_float4(0.f, 0.f, 0.f, 0.f);
            }
            __nv_bfloat16* BH = BsBase + ((s + 1) & 1) * G1_BSTRIDE;
            __nv_bfloat16* BL = BH + 96 * SMPAD;
            #pragma unroll
            for (int i = 0; i < 3; i++) {
                int idx = tid + i * 256;
                int j = idx >> 3, c8 = idx & 7;
                cp_async16(sptr(BH + j * SMPAD + c8 * 8),
                           Bg + (size_t)j * K1B + (s + 1) * 64 + c8 * 8);
                cp_async16(sptr(BL + j * SMPAD + c8 * 8),
                           Bg + (size_t)j * K1B + 256 + (s + 1) * 64 + c8 * 8);
            }
            cp_async_commit();
        }

        const __nv_bfloat16* BsHi = BsBase + (s & 1) * G1_BSTRIDE;
        const __nv_bfloat16* BsLo = BsHi + 96 * SMPAD;
        #pragma unroll
        for (int ks = 0; ks < 4; ks++) {
            int cc = ks * 16;
            uint32_t ah[2][4], al[2][4];
            #pragma unroll
            for (int mt = 0; mt < 2; mt++) {
                int row = warpM * 32 + mt * 16 + (lane & 15);
                int col = cc + ((lane >> 4) << 3);
                ldsm_x4(ah[mt], sptr(AsHi + row * SMPAD + col));
                ldsm_x4(al[mt], sptr(AsLo + row * SMPAD + col));
            }
            uint32_t bh[6][2], bl[6][2];
            #pragma unroll
            for (int pr = 0; pr < 3; pr++) {
                int j = warpN * 48 + pr * 16 + ((lane >> 4) << 3) + (lane & 7);
                int col = cc + (((lane >> 3) & 1) << 3);
                uint32_t t4[4];
                ldsm_x4(t4, sptr(BsHi + j * SMPAD + col));
                bh[pr * 2][0] = t4[0]; bh[pr * 2][1] = t4[1];
                bh[pr * 2 + 1][0] = t4[2]; bh[pr * 2 + 1][1] = t4[3];
                ldsm_x4(t4, sptr(BsLo + j * SMPAD + col));
                bl[pr * 2][0] = t4[0]; bl[pr * 2][1] = t4[1];
                bl[pr * 2 + 1][0] = t4[2]; bl[pr * 2 + 1][1] = t4[3];
            }
            #pragma unroll
            for (int mt = 0; mt < 2; mt++)
                #pragma unroll
                for (int nt = 0; nt < 6; nt++) {
                    mma_bf16(acc[mt][nt], ah[mt], bh[nt]);
                    mma_bf16(acc[mt][nt], ah[mt], bl[nt]);
                    mma_bf16(acc[mt][nt], al[mt], bh[nt]);
                }
        }
        __syncthreads();
    }

    // fused epilogue: z | r -> rh | t-partial  (jc = global gate column)
    #pragma unroll
    for (int mt = 0; mt < 2; mt++) {
        int r0 = n0 + warpM * 32 + mt * 16 + (lane >> 2);
        #pragma unroll
        for (int nt = 0; nt < 6; nt++) {
            int jc0 = gHalf * 96 + warpN * 48 + nt * 8 + (lane & 3) * 2;
            #pragma unroll
            for (int q = 0; q < 4; q++) {
                int row = r0 + ((q >> 1) << 3);
                int jc  = jc0 + (q & 1);
                if (row < N) {
                    float v = acc[mt][nt][q] + g_bias1[l * 192 + jc];
                    int jj = jc & 63;
                    size_t o = (size_t)row * HDIM + jj;
                    if (jc < 64) {
                        g_Z[o] = sigm(v);
                    } else if (jc < 128) {
                        float r = sigm(v);
                        g_RH[o] = r * hptr[o];
                    } else {
                        g_TP[o] = v;
                    }
                }
            }
        }
    }
}

// ---------------- GEMM 2: gate 5 + GRU combine, pipelined ------------------
// 256 threads, 8 warps (4M x 2N), BM=128, BN=64
#define G2_BSTRIDE (2 * 64 * SMPAD)
#define GEMM2_SMEM ((2 * 128 * SMPAD + 2 * G2_BSTRIDE) * 2)   // 73728 bytes

__global__ void __launch_bounds__(256) k_gemm2(int N, int l,
                                               const float* __restrict__ hptr,
                                               float* __restrict__ out) {
    extern __shared__ __nv_bfloat16 sm[];
    __nv_bfloat16* AsHi = sm;
    __nv_bfloat16* AsLo = AsHi + 128 * SMPAD;
    __nv_bfloat16* BsBase = AsLo + 128 * SMPAD;

    int n0 = blockIdx.x * BM;
    int tid = threadIdx.x;
    int wid = tid >> 5, lane = tid & 31;
    int warpM = wid >> 1, warpN = wid & 1;

    float acc[2][4][4];
    #pragma unroll
    for (int mt = 0; mt < 2; mt++)
        #pragma unroll
        for (int nt = 0; nt < 4; nt++)
            #pragma unroll
            for (int q = 0; q < 4; q++) acc[mt][nt][q] = 0.f;

    const __nv_bfloat16* Bg = g_Bt2 + (size_t)l * 64 * K2B;

    float4 aPre[8];
    #pragma unroll
    for (int i = 0; i < 8; i++) {
        int idx = tid + i * 256;
        int r = idx >> 4, q4 = idx & 15;
        aPre[i] = (n0 + r < N)
                ? *(const float4*)(g_AG2 + (size_t)(n0 + r) * HDIM + q4 * 4)
                : make_float4(0.f, 0.f, 0.f, 0.f);
    }
    {
        __nv_bfloat16* BH = BsBase;
        __nv_bfloat16* BL = BsBase + 64 * SMPAD;
        #pragma unroll
        for (int i = 0; i < 2; i++) {
            int idx = tid + i * 256;
            int j = idx >> 3, c8 = idx & 7;
            cp_async16(sptr(BH + j * SMPAD + c8 * 8), Bg + (size_t)j * K2B + c8 * 8);
            cp_async16(sptr(BL + j * SMPAD + c8 * 8), Bg + (size_t)j * K2B + 128 + c8 * 8);
        }
        cp_async_commit();
    }

    // source order: 0=agg_rh 1=rh
    #pragma unroll 1
    for (int s = 0; s < 2; s++) {
        #pragma unroll
        for (int i = 0; i < 8; i++) {
            int idx = tid + i * 256;
            int r = idx >> 4, q4 = idx & 15;
            uint32_t h0, l0, h1, l1;
            split_pack2(aPre[i].x, aPre[i].y, h0, l0);
            split_pack2(aPre[i].z, aPre[i].w, h1, l1);
            *(uint2*)(AsHi + r * SMPAD + q4 * 4) = make_uint2(h0, h1);
            *(uint2*)(AsLo + r * SMPAD + q4 * 4) = make_uint2(l0, l1);
        }
        cp_async_wait_all();
        __syncthreads();

        if (s < 1) {
            #pragma unroll
            for (int i = 0; i < 8; i++) {
                int idx = tid + i * 256;
                int r = idx >> 4, q4 = idx & 15;
                aPre[i] = (n0 + r < N)
                        ? *(const float4*)(g_RH + (size_t)(n0 + r) * HDIM + q4 * 4)
                        : make_float4(0.f, 0.f, 0.f, 0.f);
            }
            __nv_bfloat16* BH = BsBase + G2_BSTRIDE;
            __nv_bfloat16* BL = BH + 64 * SMPAD;
            #pragma unroll
            for (int i = 0; i < 2; i++) {
                int idx = tid + i * 256;
                int j = idx >> 3, c8 = idx & 7;
                cp_async16(sptr(BH + j * SMPAD + c8 * 8),
                           Bg + (size_t)j * K2B + 64 + c8 * 8);
                cp_async16(sptr(BL + j * SMPAD + c8 * 8),
                           Bg + (size_t)j * K2B + 128 + 64 + c8 * 8);
            }
            cp_async_commit();
        }

        const __nv_bfloat16* BsHi = BsBase + (s & 1) * G2_BSTRIDE;
        const __nv_bfloat16* BsLo = BsHi + 64 * SMPAD;
        #pragma unroll
        for (int ks = 0; ks < 4; ks++) {
            int cc = ks * 16;
            uint32_t ah[2][4], al[2][4];
            #pragma unroll
            for (int mt = 0; mt < 2; mt++) {
                int row = warpM * 32 + mt * 16 + (lane & 15);
                int col = cc + ((lane >> 4) << 3);
                ldsm_x4(ah[mt], sptr(AsHi + row * SMPAD + col));
                ldsm_x4(al[mt], sptr(AsLo + row * SMPAD + col));
            }
            uint32_t bh[4][2], bl[4][2];
            #pragma unroll
            for (int pr = 0; pr < 2; pr++) {
                int j = warpN * 32 + pr * 16 + ((lane >> 4) << 3) + (lane & 7);
                int col = cc + (((lane >> 3) & 1) << 3);
                uint32_t t4[4];
                ldsm_x4(t4, sptr(BsHi + j * SMPAD + col));
                bh[pr * 2][0] = t4[0]; bh[pr * 2][1] = t4[1];
                bh[pr * 2 + 1][0] = t4[2]; bh[pr * 2 + 1][1] = t4[3];
                ldsm_x4(t4, sptr(BsLo + j * SMPAD + col));
                bl[pr * 2][0] = t4[0]; bl[pr * 2][1] = t4[1];
                bl[pr * 2 + 1][0] = t4[2]; bl[pr * 2 + 1][1] = t4[3];
            }
            #pragma unroll
            for (int mt = 0; mt < 2; mt++)
                #pragma unroll
                for (int nt = 0; nt < 4; nt++) {
                    mma_bf16(acc[mt][nt], ah[mt], bh[nt]);
                    mma_bf16(acc[mt][nt], ah[mt], bl[nt]);
                    mma_bf16(acc[mt][nt], al[mt], bh[nt]);
                }
        }
        __syncthreads();
    }

    #pragma unroll
    for (int mt = 0; mt < 2; mt++) {
        int r0 = n0 + warpM * 32 + mt * 16 + (lane >> 2);
        #pragma unroll
        for (int nt = 0; nt < 4; nt++) {
            int jc0 = warpN * 32 + nt * 8 + (lane & 3) * 2;
            #pragma unroll
            for (int q = 0; q < 4; q++) {
                int row = r0 + ((q >> 1) << 3);
                int jc  = jc0 + (q & 1);
                if (row < N) {
                    size_t o = (size_t)row * HDIM + jc;
                    float v = acc[mt][nt][q] + g_bias2[l * 64 + jc] + g_TP[o];
                    float t = fast_tanh(v);
                    float z = g_Z[o];
                    float hv = hptr[o];
                    out[(size_t)l * N * HDIM + o] = z * hv + (1.0f - z) * t;
                }
            }
        }
    }
}

// ---------------- launch ----------------------------------------------------
extern "C" void kernel_launch(void* const* d_in, const int* in_sizes, int n_in,
                              void* d_out, int out_size) {
    const float* inp = (const float*)d_in[0];
    const int*   edg = (const int*)d_in[1];   // int64 in reference -> int32 in harness
    const float* h   = (const float*)d_in[2];
    const float* Wl  = (const float*)d_in[3];
    const float* b   = (const float*)d_in[4];
    const float* Wr  = (const float*)d_in[5];
    float* out = (float*)d_out;

    int N = in_sizes[0] / HDIM;
    int E = in_sizes[1] / 2;
    int L = in_sizes[2] / in_sizes[0];
    if (N > NMAX || E > EMAX || L > LMAX) return;

    (void)cudaFuncSetAttribute(k_gemm1, cudaFuncAttributeMaxDynamicSharedMemorySize, GEMM1_SMEM);
    (void)cudaFuncSetAttribute(k_gemm2, cudaFuncAttributeMaxDynamicSharedMemorySize, GEMM2_SMEM);

    int scanBlocks = (N + 255) / 256;

    // CSR build (vector path needs E % 4 == 0 for aligned int4 of dst block)
    k_zero_deg<<<(N + 255) / 256, 256>>>(N);
    if ((E & 3) == 0) {
        int t4 = E / 4;
        k_count4<<<(t4 + 255) / 256, 256>>>(edg, E, N);
    } else {
        k_count<<<(E + 255) / 256, 256>>>(edg, E, N);
    }
    k_scan1<<<scanBlocks, 256>>>(N);
    k_scan2<<<1, 512>>>(scanBlocks, N);
    k_scan3<<<scanBlocks, 256>>>(N);
    if ((E & 3) == 0) {
        int t4 = E / 4;
        k_scatter4<<<(t4 + 255) / 256, 256>>>(edg, E, N);
    } else {
        k_scatter<<<(E + 255) / 256, 256>>>(edg, E, N);
    }

    // weight + bias packing
    int packTotal = L * 192 * K1B + L * 64 * K2B + L * 256;
    k_packAll<<<(packTotal + 255) / 256, 256>>>(Wl, b, Wr, L);

    int aggBlocks = (N * 32 + 255) / 256;
    int rowTiles  = (N + BM - 1) / BM;

    const float* x = inp;
    for (int l = 0; l < L; l++) {
        const float* hl = h + (size_t)l * N * HDIM;
        k_agg1<<<aggBlocks, 256>>>(x, hl, N);
        dim3 g1(rowTiles, 2);
        k_gemm1<<<g1, 256, GEMM1_SMEM>>>(N, l, x, hl);
        k_agg2<<<aggBlocks, 256>>>(N);
        k_gemm2<<<rowTiles, 256, GEMM2_SMEM>>>(N, l, hl, out);
        x = out + (size_t)l * N * HDIM;
    }
}

// round 17
// speedup vs baseline: 1.2222x; 1.2222x over previous
#include <cuda_runtime.h>
#include <cuda_bf16.h>
#include <cstdint>
#include <math.h>

#define NMAX 100000
#define EMAX 1600000
#define HDIM 64
#define LMAX 2
#define K1B 512   // B1 row: [hi(4x64) | lo(4x64)]
#define K2B 256   // B2 row: [hi(2x64) | lo(2x64)]

// ---------------- scratch (static device memory) ---------------------------
__device__ __align__(16) int   g_deg[NMAX];
__device__ __align__(16) int   g_rowptr[NMAX + 1];
__device__ __align__(16) int   g_cursor[NMAX];
__device__ __align__(16) int   g_csr[EMAX];
__device__ __align__(16) float g_invdeg[NMAX];
__device__ __align__(16) int   g_bsum[512];

__device__ __align__(16) float g_AGX[(size_t)NMAX * HDIM];  // mean-agg of x
__device__ __align__(16) float g_AGH[(size_t)NMAX * HDIM];  // mean-agg of h
__device__ __align__(16) float g_AG2[(size_t)NMAX * HDIM];  // mean-agg of r*h
__device__ __align__(16) float g_Z [(size_t)NMAX * HDIM];
__device__ __align__(16) float g_TP[(size_t)NMAX * HDIM];
__device__ __align__(16) float g_RH[(size_t)NMAX * HDIM];

__device__ __align__(16) __nv_bfloat16 g_Bt1[(size_t)LMAX * 192 * K1B];
__device__ __align__(16) __nv_bfloat16 g_Bt2[(size_t)LMAX * 64 * K2B];
__device__ __align__(16) float g_bias1[LMAX * 192];
__device__ __align__(16) float g_bias2[LMAX * 64];

// ---------------- helpers --------------------------------------------------
__device__ __forceinline__ float sigm(float x) { return 1.0f / (1.0f + __expf(-x)); }
__device__ __forceinline__ float fast_tanh(float x) {
    float xc = fminf(fmaxf(x, -30.0f), 30.0f);
    return 1.0f - __fdividef(2.0f, __expf(2.0f * xc) + 1.0f);
}

__device__ __forceinline__ void mma_bf16(float (&d)[4], const uint32_t (&a)[4],
                                         const uint32_t (&b)[2]) {
    asm volatile(
        "mma.sync.aligned.m16n8k16.row.col.f32.bf16.bf16.f32 "
        "{%0,%1,%2,%3}, {%4,%5,%6,%7}, {%8,%9}, {%0,%1,%2,%3};\n"
        : "+f"(d[0]), "+f"(d[1]), "+f"(d[2]), "+f"(d[3])
        : "r"(a[0]), "r"(a[1]), "r"(a[2]), "r"(a[3]), "r"(b[0]), "r"(b[1]));
}
__device__ __forceinline__ uint32_t sptr(const void* p) {
    return (uint32_t)__cvta_generic_to_shared(p);
}
__device__ __forceinline__ void ldsm_x4(uint32_t (&r)[4], uint32_t addr) {
    asm volatile("ldmatrix.sync.aligned.m8n8.x4.shared.b16 {%0,%1,%2,%3}, [%4];\n"
                 : "=r"(r[0]), "=r"(r[1]), "=r"(r[2]), "=r"(r[3]) : "r"(addr));
}
__device__ __forceinline__ void cp_async16(uint32_t dst, const void* src) {
    asm volatile("cp.async.cg.shared.global [%0], [%1], 16;\n" :: "r"(dst), "l"(src));
}
__device__ __forceinline__ void cp_async_commit() {
    asm volatile("cp.async.commit_group;\n");
}
__device__ __forceinline__ void cp_async_wait_all() {
    asm volatile("cp.async.wait_group 0;\n" ::: "memory");
}
__device__ __forceinline__ void split_pack2(float a, float b, uint32_t& hi2, uint32_t& lo2) {
    __nv_bfloat16 ha = __float2bfloat16_rn(a), hb = __float2bfloat16_rn(b);
    __nv_bfloat16 la = __float2bfloat16_rn(a - __bfloat162float(ha));
    __nv_bfloat16 lb = __float2bfloat16_rn(b - __bfloat162float(hb));
    hi2 = ((uint32_t)__bfloat16_as_ushort(hb) << 16) | __bfloat16_as_ushort(ha);
    lo2 = ((uint32_t)__bfloat16_as_ushort(lb) << 16) | __bfloat16_as_ushort(la);
}

// ---------------- CSR build ------------------------------------------------
__global__ void k_zero_deg(int N) {
    int i = blockIdx.x * blockDim.x + threadIdx.x;
    if (i < N) g_deg[i] = 0;
}

__global__ void k_count(const int* __restrict__ edg, int E, int N) {
    int e = blockIdx.x * blockDim.x + threadIdx.x;
    if (e < E) {
        int dst = edg[E + e];
        if ((unsigned)dst < (unsigned)N) atomicAdd(&g_deg[dst], 1);
    }
}

// parallel 3-phase scan
__global__ void k_scan1(int N) {
    __shared__ int ws[8];
    int tid = threadIdx.x, lane = tid & 31, wid = tid >> 5;
    int i = blockIdx.x * 256 + tid;
    int v = (i < N) ? g_deg[i] : 0;
    int x = v;
    #pragma unroll
    for (int o = 1; o < 32; o <<= 1) x += __shfl_down_sync(0xffffffffu, x, o);
    if (lane == 0) ws[wid] = x;
    __syncthreads();
    if (tid == 0) {
        int s = 0;
        #pragma unroll
        for (int w = 0; w < 8; w++) s += ws[w];
        g_bsum[blockIdx.x] = s;
    }
}

__global__ void k_scan2(int nb, int N) {
    __shared__ int ws[16];
    int tid = threadIdx.x, lane = tid & 31, wid = tid >> 5;
    int v = (tid < nb) ? g_bsum[tid] : 0;
    int x = v;
    #pragma unroll
    for (int o = 1; o < 32; o <<= 1) {
        int y = __shfl_up_sync(0xffffffffu, x, o);
        if (lane >= o) x += y;
    }
    if (lane == 31) ws[wid] = x;
    __syncthreads();
    if (wid == 0 && lane < 16) {
        int w = ws[lane];
        #pragma unroll
        for (int o = 1; o < 16; o <<= 1) {
            int y = __shfl_up_sync(0xffffu, w, o);
            if (lane >= o) w += y;
        }
        ws[lane] = w;
    }
    __syncthreads();
    int excl = x - v + (wid > 0 ? ws[wid - 1] : 0);
    if (tid < nb) g_bsum[tid] = excl;
    if (tid == nb - 1) g_rowptr[N] = excl + v;
}

__global__ void k_scan3(int N) {
    __shared__ int ws[8];
    int tid = threadIdx.x, lane = tid & 31, wid = tid >> 5;
    int i = blockIdx.x * 256 + tid;
    int v = (i < N) ? g_deg[i] : 0;
    int x = v;
    #pragma unroll
    for (int o = 1; o < 32; o <<= 1) {
        int y = __shfl_up_sync(0xffffffffu, x, o);
        if (lane >= o) x += y;
    }
    if (lane == 31) ws[wid] = x;
    __syncthreads();
    if (wid == 0 && lane < 8) {
        int w = ws[lane];
        #pragma unroll
        for (int o = 1; o < 8; o <<= 1) {
            int y = __shfl_up_sync(0xffu, w, o);
            if (lane >= o) w += y;
        }
        ws[lane] = w;
    }
    __syncthreads();
    if (i < N) {
        int excl = x - v + (wid > 0 ? ws[wid - 1] : 0) + g_bsum[blockIdx.x];
        g_rowptr[i] = excl;
        g_cursor[i] = excl;
        g_invdeg[i] = (v > 0) ? 1.0f / (float)v : 0.0f;
    }
}

// scatter + weight/bias packing fused into one launch (independent work,
// disjoint block ranges). Blocks [0, sBlocks) scatter; the rest pack.
__global__ void k_scatter_pack(const int* __restrict__ edg, int E, int N, int sBlocks,
                               const float* __restrict__ Wl, const float* __restrict__ b,
                               const float* __restrict__ Wr, int L) {
    if (blockIdx.x < (unsigned)sBlocks) {
        int e = blockIdx.x * blockDim.x + threadIdx.x;
        if (e < E) {
            int src = edg[e];
            int dst = edg[E + e];
            if ((unsigned)src < (unsigned)N && (unsigned)dst < (unsigned)N) {
                int pos = atomicAdd(&g_cursor[dst], 1);
                g_csr[pos] = src;
            }
        }
        return;
    }
    int idx = (blockIdx.x - sBlocks) * blockDim.x + threadIdx.x;
    int t1 = L * 192 * K1B;
    int t2 = L * 64 * K2B;
    int t3 = L * 256;
    if (idx < t1) {
        int k = idx % K1B;
        int j = (idx / K1B) % 192;
        int l = idx / (K1B * 192);
        int t = k / 256, rem = k % 256, s = rem / 64, c = rem % 64;
        int g = j / 64, jj = j % 64;
        int gbase = 2 * g;
        float w = 0.0f;
        if (s == 0)      w = Wl[(((size_t)l * 6 + gbase) * 64 + jj) * 64 + c];
        else if (s == 1) w = Wr[(((size_t)l * 6 + gbase) * 64 + jj) * 64 + c];
        else if (s == 2) { if (g < 2) w = Wl[(((size_t)l * 6 + gbase + 1) * 64 + jj) * 64 + c]; }
        else             { if (g < 2) w = Wr[(((size_t)l * 6 + gbase + 1) * 64 + jj) * 64 + c]; }
        __nv_bfloat16 hi = __float2bfloat16_rn(w);
        __nv_bfloat16 val = (t == 1) ? __float2bfloat16_rn(w - __bfloat162float(hi)) : hi;
        g_Bt1[(size_t)(l * 192 + j) * K1B + k] = val;
    } else if (idx < t1 + t2) {
        int i2 = idx - t1;
        int k = i2 % K2B;
        int j = (i2 / K2B) % 64;
        int l = i2 / (K2B * 64);
        int t = k / 128, rem = k % 128, s = rem / 64, c = rem % 64;
        const float* W = s ? Wr : Wl;
        float w = W[(((size_t)l * 6 + 5) * 64 + j) * 64 + c];
        __nv_bfloat16 hi = __float2bfloat16_rn(w);
        __nv_bfloat16 val = (t == 1) ? __float2bfloat16_rn(w - __bfloat162float(hi)) : hi;
        g_Bt2[(size_t)(l * 64 + j) * K2B + k] = val;
    } else if (idx < t1 + t2 + t3) {
        int i3 = idx - t1 - t2;
        int j = i3 % 256, l = i3 / 256;
        if (j < 192) {
            int g = j / 64, jj = j % 64;
            float v;
            if (g == 0)      v = b[((size_t)l * 6 + 0) * 64 + jj] + b[((size_t)l * 6 + 1) * 64 + jj];
            else if (g == 1) v = b[((size_t)l * 6 + 2) * 64 + jj] + b[((size_t)l * 6 + 3) * 64 + jj];
            else             v = b[((size_t)l * 6 + 4) * 64 + jj];
            g_bias1[l * 192 + j] = v;
        } else {
            int jj = j - 192;
            g_bias2[l * 64 + jj] = b[((size_t)l * 6 + 5) * 64 + jj];
        }
    }
}

// ---------------- aggregation (warp per node, scalar gather) ---------------
__global__ void k_agg1(const float* __restrict__ x, const float* __restrict__ h, int N) {
    int warp = (blockIdx.x * blockDim.x + threadIdx.x) >> 5;
    if (warp >= N) return;
    int lane = threadIdx.x & 31;
    int beg = g_rowptr[warp], end = g_rowptr[warp + 1];
    float sx0 = 0.f, sx1 = 0.f, sh0 = 0.f, sh1 = 0.f;
    int e = beg;
    for (; e + 1 < end; e += 2) {
        int s0 = g_csr[e], s1 = g_csr[e + 1];
        const float* xr0 = x + (size_t)s0 * HDIM;
        const float* hr0 = h + (size_t)s0 * HDIM;
        const float* xr1 = x + (size_t)s1 * HDIM;
        const float* hr1 = h + (size_t)s1 * HDIM;
        sx0 += xr0[lane] + xr1[lane];
        sx1 += xr0[lane + 32] + xr1[lane + 32];
        sh0 += hr0[lane] + hr1[lane];
        sh1 += hr0[lane + 32] + hr1[lane + 32];
    }
    if (e < end) {
        int s = g_csr[e];
        const float* xr = x + (size_t)s * HDIM;
        const float* hr = h + (size_t)s * HDIM;
        sx0 += xr[lane];  sx1 += xr[lane + 32];
        sh0 += hr[lane];  sh1 += hr[lane + 32];
    }
    float inv = g_invdeg[warp];
    size_t o = (size_t)warp * HDIM;
    g_AGX[o + lane] = sx0 * inv;  g_AGX[o + lane + 32] = sx1 * inv;
    g_AGH[o + lane] = sh0 * inv;  g_AGH[o + lane + 32] = sh1 * inv;
}

__global__ void k_agg2(int N) {
    int warp = (blockIdx.x * blockDim.x + threadIdx.x) >> 5;
    if (warp >= N) return;
    int lane = threadIdx.x & 31;
    int beg = g_rowptr[warp], end = g_rowptr[warp + 1];
    float s0 = 0.f, s1 = 0.f;
    int e = beg;
    for (; e + 1 < end; e += 2) {
        const float* r0 = g_RH + (size_t)g_csr[e] * HDIM;
        const float* r1 = g_RH + (size_t)g_csr[e + 1] * HDIM;
        s0 += r0[lane] + r1[lane];
        s1 += r0[lane + 32] + r1[lane + 32];
    }
    if (e < end) {
        const float* rr = g_RH + (size_t)g_csr[e] * HDIM;
        s0 += rr[lane];
        s1 += rr[lane + 32];
    }
    float inv = g_invdeg[warp];
    size_t o = (size_t)warp * HDIM;
    g_AG2[o + lane] = s0 * inv;
    g_AG2[o + lane + 32] = s1 * inv;
}

// ---------------- GEMM 1: all gates, pipelined A-prefetch + cp.async B -----
// 512 threads, 16 warps (4M x 4N), BM=128, BN=192, warp tile 32x48
#define BM 128
#define SMPAD 72
#define G1_BSTRIDE (2 * 192 * SMPAD)
#define GEMM1_SMEM ((2 * 128 * SMPAD + 2 * G1_BSTRIDE) * 2)   // 147456 bytes

__global__ void __launch_bounds__(512) k_gemm1(int N, int l,
                                               const float* __restrict__ xptr,
                                               const float* __restrict__ hptr) {
    extern __shared__ __nv_bfloat16 sm[];
    __nv_bfloat16* AsHi = sm;
    __nv_bfloat16* AsLo = AsHi + 128 * SMPAD;
    __nv_bfloat16* BsBase = AsLo + 128 * SMPAD;

    int n0 = blockIdx.x * BM;
    int tid = threadIdx.x;
    int wid = tid >> 5, lane = tid & 31;
    int warpM = wid >> 2, warpN = wid & 3;

    float acc[2][6][4];
    #pragma unroll
    for (int mt = 0; mt < 2; mt++)
        #pragma unroll
        for (int nt = 0; nt < 6; nt++)
            #pragma unroll
            for (int q = 0; q < 4; q++) acc[mt][nt][q] = 0.f;

    const __nv_bfloat16* Bg = g_Bt1 + (size_t)l * 192 * K1B;

    float4 aPre[4];
    #pragma unroll
    for (int i = 0; i < 4; i++) {
        int idx = tid + i * 512;
        int r = idx >> 4, q4 = idx & 15;
        aPre[i] = (n0 + r < N)
                ? *(const float4*)(g_AGX + (size_t)(n0 + r) * HDIM + q4 * 4)
                : make_float4(0.f, 0.f, 0.f, 0.f);
    }
    {
        __nv_bfloat16* BH = BsBase;
        __nv_bfloat16* BL = BsBase + 192 * SMPAD;
        #pragma unroll
        for (int i = 0; i < 3; i++) {
            int idx = tid + i * 512;
            int j = idx >> 3, c8 = idx & 7;
            cp_async16(sptr(BH + j * SMPAD + c8 * 8), Bg + (size_t)j * K1B + c8 * 8);
            cp_async16(sptr(BL + j * SMPAD + c8 * 8), Bg + (size_t)j * K1B + 256 + c8 * 8);
        }
        cp_async_commit();
    }

    // source order: 0=aggx 1=x 2=aggh 3=h
    #pragma unroll 1
    for (int s = 0; s < 4; s++) {
        #pragma unroll
        for (int i = 0; i < 4; i++) {
            int idx = tid + i * 512;
            int r = idx >> 4, q4 = idx & 15;
            uint32_t h0, l0, h1, l1;
            split_pack2(aPre[i].x, aPre[i].y, h0, l0);
            split_pack2(aPre[i].z, aPre[i].w, h1, l1);
            *(uint2*)(AsHi + r * SMPAD + q4 * 4) = make_uint2(h0, h1);
            *(uint2*)(AsLo + r * SMPAD + q4 * 4) = make_uint2(l0, l1);
        }
        cp_async_wait_all();
        __syncthreads();

        if (s < 3) {
            const float* Snext = (s == 0) ? xptr : (s == 1) ? g_AGH : hptr;
            #pragma unroll
            for (int i = 0; i < 4; i++) {
                int idx = tid + i * 512;
                int r = idx >> 4, q4 = idx & 15;
                aPre[i] = (n0 + r < N)
                        ? *(const float4*)(Snext + (size_t)(n0 + r) * HDIM + q4 * 4)
                        : make_float4(0.f, 0.f, 0.f, 0.f);
            }
            __nv_bfloat16* BH = BsBase + ((s + 1) & 1) * G1_BSTRIDE;
            __nv_bfloat16* BL = BH + 192 * SMPAD;
            #pragma unroll
            for (int i = 0; i < 3; i++) {
                int idx = tid + i * 512;
                int j = idx >> 3, c8 = idx & 7;
                cp_async16(sptr(BH + j * SMPAD + c8 * 8),
                           Bg + (size_t)j * K1B + (s + 1) * 64 + c8 * 8);
                cp_async16(sptr(BL + j * SMPAD + c8 * 8),
                           Bg + (size_t)j * K1B + 256 + (s + 1) * 64 + c8 * 8);
            }
            cp_async_commit();
        }

        const __nv_bfloat16* BsHi = BsBase + (s & 1) * G1_BSTRIDE;
        const __nv_bfloat16* BsLo = BsHi + 192 * SMPAD;
        #pragma unroll
        for (int ks = 0; ks < 4; ks++) {
            int cc = ks * 16;
            uint32_t ah[2][4], al[2][4];
            #pragma unroll
            for (int mt = 0; mt < 2; mt++) {
                int row = warpM * 32 + mt * 16 + (lane & 15);
                int col = cc + ((lane >> 4) << 3);
                ldsm_x4(ah[mt], sptr(AsHi + row * SMPAD + col));
                ldsm_x4(al[mt], sptr(AsLo + row * SMPAD + col));
            }
            uint32_t bh[6][2], bl[6][2];
            #pragma unroll
            for (int pr = 0; pr < 3; pr++) {
                int j = warpN * 48 + pr * 16 + ((lane >> 4) << 3) + (lane & 7);
                int col = cc + (((lane >> 3) & 1) << 3);
                uint32_t t4[4];
                ldsm_x4(t4, sptr(BsHi + j * SMPAD + col));
                bh[pr * 2][0] = t4[0]; bh[pr * 2][1] = t4[1];
                bh[pr * 2 + 1][0] = t4[2]; bh[pr * 2 + 1][1] = t4[3];
                ldsm_x4(t4, sptr(BsLo + j * SMPAD + col));
                bl[pr * 2][0] = t4[0]; bl[pr * 2][1] = t4[1];
                bl[pr * 2 + 1][0] = t4[2]; bl[pr * 2 + 1][1] = t4[3];
            }
            #pragma unroll
            for (int mt = 0; mt < 2; mt++)
                #pragma unroll
                for (int nt = 0; nt < 6; nt++) {
                    mma_bf16(acc[mt][nt], ah[mt], bh[nt]);
                    mma_bf16(acc[mt][nt], ah[mt], bl[nt]);
                    mma_bf16(acc[mt][nt], al[mt], bh[nt]);
                }
        }
        __syncthreads();
    }

    // fused epilogue (float2 stores): z | r -> rh | t-partial
    #pragma unroll
    for (int mt = 0; mt < 2; mt++) {
        int r0 = n0 + warpM * 32 + mt * 16 + (lane >> 2);
        #pragma unroll
        for (int nt = 0; nt < 6; nt++) {
            int jc0 = warpN * 48 + nt * 8 + (lane & 3) * 2;   // even
            float2 bia = *(const float2*)&g_bias1[l * 192 + jc0];
            int jj = jc0 & 63;
            #pragma unroll
            for (int half = 0; half < 2; half++) {
                int row = r0 + half * 8;
                if (row >= N) continue;
                float v0 = acc[mt][nt][half * 2 + 0] + bia.x;
                float v1 = acc[mt][nt][half * 2 + 1] + bia.y;
                size_t o = (size_t)row * HDIM + jj;
                if (jc0 < 64) {
                    *(float2*)&g_Z[o] = make_float2(sigm(v0), sigm(v1));
                } else if (jc0 < 128) {
                    float2 hv = *(const float2*)&hptr[o];
                    *(float2*)&g_RH[o] = make_float2(sigm(v0) * hv.x, sigm(v1) * hv.y);
                } else {
                    *(float2*)&g_TP[o] = make_float2(v0, v1);
                }
            }
        }
    }
}

// ---------------- GEMM 2: gate 5 + GRU combine, pipelined ------------------
// 256 threads, 8 warps (4M x 2N), BM=128, BN=64
#define G2_BSTRIDE (2 * 64 * SMPAD)
#define GEMM2_SMEM ((2 * 128 * SMPAD + 2 * G2_BSTRIDE) * 2)   // 73728 bytes

__global__ void __launch_bounds__(256) k_gemm2(int N, int l,
                                               const float* __restrict__ hptr,
                                               float* __restrict__ out) {
    extern __shared__ __nv_bfloat16 sm[];
    __nv_bfloat16* AsHi = sm;
    __nv_bfloat16* AsLo = AsHi + 128 * SMPAD;
    __nv_bfloat16* BsBase = AsLo + 128 * SMPAD;

    int n0 = blockIdx.x * BM;
    int tid = threadIdx.x;
    int wid = tid >> 5, lane = tid & 31;
    int warpM = wid >> 1, warpN = wid & 1;

    float acc[2][4][4];
    #pragma unroll
    for (int mt = 0; mt < 2; mt++)
        #pragma unroll
        for (int nt = 0; nt < 4; nt++)
            #pragma unroll
            for (int q = 0; q < 4; q++) acc[mt][nt][q] = 0.f;

    const __nv_bfloat16* Bg = g_Bt2 + (size_t)l * 64 * K2B;

    float4 aPre[8];
    #pragma unroll
    for (int i = 0; i < 8; i++) {
        int idx = tid + i * 256;
        int r = idx >> 4, q4 = idx & 15;
        aPre[i] = (n0 + r < N)
                ? *(const float4*)(g_AG2 + (size_t)(n0 + r) * HDIM + q4 * 4)
                : make_float4(0.f, 0.f, 0.f, 0.f);
    }
    {
        __nv_bfloat16* BH = BsBase;
        __nv_bfloat16* BL = BsBase + 64 * SMPAD;
        #pragma unroll
        for (int i = 0; i < 2; i++) {
            int idx = tid + i * 256;
            int j = idx >> 3, c8 = idx & 7;
            cp_async16(sptr(BH + j * SMPAD + c8 * 8), Bg + (size_t)j * K2B + c8 * 8);
            cp_async16(sptr(BL + j * SMPAD + c8 * 8), Bg + (size_t)j * K2B + 128 + c8 * 8);
        }
        cp_async_commit();
    }

    // source order: 0=agg_rh 1=rh
    #pragma unroll 1
    for (int s = 0; s < 2; s++) {
        #pragma unroll
        for (int i = 0; i < 8; i++) {
            int idx = tid + i * 256;
            int r = idx >> 4, q4 = idx & 15;
            uint32_t h0, l0, h1, l1;
            split_pack2(aPre[i].x, aPre[i].y, h0, l0);
            split_pack2(aPre[i].z, aPre[i].w, h1, l1);
            *(uint2*)(AsHi + r * SMPAD + q4 * 4) = make_uint2(h0, h1);
            *(uint2*)(AsLo + r * SMPAD + q4 * 4) = make_uint2(l0, l1);
        }
        cp_async_wait_all();
        __syncthreads();

        if (s < 1) {
            #pragma unroll
            for (int i = 0; i < 8; i++) {
                int idx = tid + i * 256;
                int r = idx >> 4, q4 = idx & 15;
                aPre[i] = (n0 + r < N)
                        ? *(const float4*)(g_RH + (size_t)(n0 + r) * HDIM + q4 * 4)
                        : make_float4(0.f, 0.f, 0.f, 0.f);
            }
            __nv_bfloat16* BH = BsBase + G2_BSTRIDE;
            __nv_bfloat16* BL = BH + 64 * SMPAD;
            #pragma unroll
            for (int i = 0; i < 2; i++) {
                int idx = tid + i * 256;
                int j = idx >> 3, c8 = idx & 7;
                cp_async16(sptr(BH + j * SMPAD + c8 * 8),
                           Bg + (size_t)j * K2B + 64 + c8 * 8);
                cp_async16(sptr(BL + j * SMPAD + c8 * 8),
                           Bg + (size_t)j * K2B + 128 + 64 + c8 * 8);
            }
            cp_async_commit();
        }

        const __nv_bfloat16* BsHi = BsBase + (s & 1) * G2_BSTRIDE;
        const __nv_bfloat16* BsLo = BsHi + 64 * SMPAD;
        #pragma unroll
        for (int ks = 0; ks < 4; ks++) {
            int cc = ks * 16;
            uint32_t ah[2][4], al[2][4];
            #pragma unroll
            for (int mt = 0; mt < 2; mt++) {
                int row = warpM * 32 + mt * 16 + (lane & 15);
                int col = cc + ((lane >> 4) << 3);
                ldsm_x4(ah[mt], sptr(AsHi + row * SMPAD + col));
                ldsm_x4(al[mt], sptr(AsLo + row * SMPAD + col));
            }
            uint32_t bh[4][2], bl[4][2];
            #pragma unroll
            for (int pr = 0; pr < 2; pr++) {
                int j = warpN * 32 + pr * 16 + ((lane >> 4) << 3) + (lane & 7);
                int col = cc + (((lane >> 3) & 1) << 3);
                uint32_t t4[4];
                ldsm_x4(t4, sptr(BsHi + j * SMPAD + col));
                bh[pr * 2][0] = t4[0]; bh[pr * 2][1] = t4[1];
                bh[pr * 2 + 1][0] = t4[2]; bh[pr * 2 + 1][1] = t4[3];
                ldsm_x4(t4, sptr(BsLo + j * SMPAD + col));
                bl[pr * 2][0] = t4[0]; bl[pr * 2][1] = t4[1];
                bl[pr * 2 + 1][0] = t4[2]; bl[pr * 2 + 1][1] = t4[3];
            }
            #pragma unroll
            for (int mt = 0; mt < 2; mt++)
                #pragma unroll
                for (int nt = 0; nt < 4; nt++) {
                    mma_bf16(acc[mt][nt], ah[mt], bh[nt]);
                    mma_bf16(acc[mt][nt], ah[mt], bl[nt]);
                    mma_bf16(acc[mt][nt], al[mt], bh[nt]);
                }
        }
        __syncthreads();
    }

    // epilogue (float2): tanh + GRU combine
    #pragma unroll
    for (int mt = 0; mt < 2; mt++) {
        int r0 = n0 + warpM * 32 + mt * 16 + (lane >> 2);
        #pragma unroll
        for (int nt = 0; nt < 4; nt++) {
            int jc0 = warpN * 32 + nt * 8 + (lane & 3) * 2;   // even
            float2 bia = *(const float2*)&g_bias2[l * 64 + jc0];
            #pragma unroll
            for (int half = 0; half < 2; half++) {
                int row = r0 + half * 8;
                if (row >= N) continue;
                size_t o = (size_t)row * HDIM + jc0;
                float2 tp = *(const float2*)&g_TP[o];
                float2 zz = *(const float2*)&g_Z[o];
                float2 hv = *(const float2*)&hptr[o];
                float t0 = fast_tanh(acc[mt][nt][half * 2 + 0] + bia.x + tp.x);
                float t1 = fast_tanh(acc[mt][nt][half * 2 + 1] + bia.y + tp.y);
                float o0 = zz.x * hv.x + (1.0f - zz.x) * t0;
                float o1 = zz.y * hv.y + (1.0f - zz.y) * t1;
                *(float2*)&out[(size_t)l * N * HDIM + o] = make_float2(o0, o1);
            }
        }
    }
}

// ---------------- launch ----------------------------------------------------
extern "C" void kernel_launch(void* const* d_in, const int* in_sizes, int n_in,
                              void* d_out, int out_size) {
    const float* inp = (const float*)d_in[0];
    const int*   edg = (const int*)d_in[1];   // int64 in reference -> int32 in harness
    const float* h   = (const float*)d_in[2];
    const float* Wl  = (const float*)d_in[3];
    const float* b   = (const float*)d_in[4];
    const float* Wr  = (const float*)d_in[5];
    float* out = (float*)d_out;

    int N = in_sizes[0] / HDIM;
    int E = in_sizes[1] / 2;
    int L = in_sizes[2] / in_sizes[0];
    if (N > NMAX || E > EMAX || L > LMAX) return;

    (void)cudaFuncSetAttribute(k_gemm1, cudaFuncAttributeMaxDynamicSharedMemorySize, GEMM1_SMEM);
    (void)cudaFuncSetAttribute(k_gemm2, cudaFuncAttributeMaxDynamicSharedMemorySize, GEMM2_SMEM);

    int scanBlocks = (N + 255) / 256;

    // CSR build
    k_zero_deg<<<(N + 255) / 256, 256>>>(N);
    k_count<<<(E + 255) / 256, 256>>>(edg, E, N);
    k_scan1<<<scanBlocks, 256>>>(N);
    k_scan2<<<1, 512>>>(scanBlocks, N);
    k_scan3<<<scanBlocks, 256>>>(N);

    // scatter + weight/bias packing fused (independent work)
    int sBlocks   = (E + 255) / 256;
    int packTotal = L * 192 * K1B + L * 64 * K2B + L * 256;
    int pBlocks   = (packTotal + 255) / 256;
    k_scatter_pack<<<sBlocks + pBlocks, 256>>>(edg, E, N, sBlocks, Wl, b, Wr, L);

    int aggBlocks = (N * 32 + 255) / 256;
    int rowTiles  = (N + BM - 1) / BM;

    const float* x = inp;
    for (int l = 0; l < L; l++) {
        const float* hl = h + (size_t)l * N * HDIM;
        k_agg1<<<aggBlocks, 256>>>(x, hl, N);
        k_gemm1<<<rowTiles, 512, GEMM1_SMEM>>>(N, l, x, hl);
        k_agg2<<<aggBlocks, 256>>>(N);
        k_gemm2<<<rowTiles, 256, GEMM2_SMEM>>>(N, l, hl, out);
        x = out + (size_t)l * N * HDIM;
    }
}